// round 2
// baseline (speedup 1.0000x reference)
#include <cuda_runtime.h>
#include <math.h>

#define S 256
#define NB 128
#define D 256
#define L 8
#define EPS 1e-8f

// ---- scratch (static device memory; no allocations anywhere) ----
__device__ __align__(16) float g_w2[6][L][D];        // W[0..5]^2
// norm slots: 0-7 full(W0/W1), 8-15 maxpool(W2/W3), 16-23 W4, 24-31 W5, 32 unweighted
__device__ __align__(16) float g_np[2][S][NB][33];   // [dir][pos][b][slot]
__device__ __align__(16) float g_nq[2][S][NB][33];
__device__ __align__(16) float g_alpha[2][NB][S][S]; // [dir][b][s][t]
__device__ __align__(16) float g_rowsum[2][NB][S];
__device__ __align__(16) int   g_amax[2][NB][S];
__device__ __align__(16) float g_h[2][NB][S][D];     // h_mean (already divided by rowsum)

// ---------------- K0: W^2 ----------------
__global__ void k_w2(const float* __restrict__ W){
  int i = blockIdx.x*blockDim.x + threadIdx.x;
  if (i < 6*L*D){ float w = W[i]; (&g_w2[0][0][0])[i] = w*w; }
}

// ---------------- K1: all weighted norms ----------------
// block=128 (4 warps). warp -> (tensor,dir). Each block processes 16 (pos,b) rows.
__global__ void __launch_bounds__(128) k_norms(const float* __restrict__ P,
                                               const float* __restrict__ Q){
  __shared__ float sw[6*L*D]; // 48KB: W^2 rows 0..5
  int tid = threadIdx.x;
  for (int i=tid; i<6*L*D; i+=128) sw[i] = (&g_w2[0][0][0])[i];
  __syncthreads();
  int warp = tid>>5, lane = tid&31;
  int tensor = warp>>1, dir = warp&1;
  const float* X = tensor ? Q : P;
  float* dst = tensor ? &g_nq[0][0][0][0] : &g_np[0][0][0][0];
  int wrow0 = dir, wrow1 = 2+dir; // full row, maxpool row; plus rows 4,5
  for (int it=0; it<16; it++){
    int r = blockIdx.x*16 + it;
    int pos = r>>7, b = r&127;
    const float* x = X + (size_t)(pos*NB+b)*512 + dir*256;
    float acc[4][L];
    #pragma unroll
    for (int a=0;a<4;a++){
      #pragma unroll
      for (int l=0;l<L;l++) acc[a][l]=0.f;
    }
    float u=0.f;
    #pragma unroll
    for (int k=0;k<8;k++){
      int d = lane + k*32;
      float v = x[d];
      float v2 = v*v;
      u += v2;
      int rows[4] = {wrow0, wrow1, 4, 5};
      #pragma unroll
      for (int a=0;a<4;a++){
        const float* wr = &sw[rows[a]*L*D + d];
        #pragma unroll
        for (int l=0;l<L;l++) acc[a][l] += v2 * wr[l*D];
      }
    }
    #pragma unroll
    for (int off=16; off; off>>=1){
      u += __shfl_down_sync(0xffffffffu, u, off);
      #pragma unroll
      for (int a=0;a<4;a++){
        #pragma unroll
        for (int l=0;l<L;l++) acc[a][l] += __shfl_down_sync(0xffffffffu, acc[a][l], off);
      }
    }
    if (lane==0){
      float* o = dst + ((size_t)(dir*S + pos)*NB + b)*33;
      #pragma unroll
      for (int a=0;a<4;a++){
        #pragma unroll
        for (int l=0;l<L;l++) o[a*8+l] = sqrtf(acc[a][l]);
      }
      o[32] = sqrtf(u);
    }
  }
}

// ---------------- K_main: 9-channel diag-weighted GEMM + maxpool + alpha stats ----------------
// grid (4 s-tiles, 128 b, 2 dir), block 256. Per CTA: 64 s x 256 t x 256 d x 9 ch.
#define SM_MAIN ((64*257 + 32*257 + 9*256 + 32*9)*4)

__global__ void __launch_bounds__(256) k_main(const float* __restrict__ P,
                                              const float* __restrict__ Q,
                                              float* __restrict__ out){
  extern __shared__ float sm[];
  float* sP  = sm;                       // [64][257]
  float* sQ  = sm + 64*257;              // [32][257]
  float* sW  = sm + 64*257 + 32*257;     // [9][256] ch 0-7: W_mp^2, ch8: 1.0
  float* sQn = sW + 9*256;               // [32][9]  q norms (mp l=0..7, unweighted)

  int sTile = blockIdx.x, b = blockIdx.y, dir = blockIdx.z;
  int sBase = sTile*64;
  int tid = threadIdx.x;
  int tx = tid & 7, ty = tid >> 3;
  int sl0 = ty*2;

  for (int i=tid;i<9*D;i+=256){
    int c=i>>8, d=i&255;
    sW[c*D+d] = (c<8) ? g_w2[2+dir][c][d] : 1.0f;
  }
  { // P tile [64 s][256 d]
    int row = tid>>2, dOff=(tid&3)*64;
    const float4* src = (const float4*)(P + (size_t)((sBase+row)*NB + b)*512 + dir*256 + dOff);
    float* dstp = sP + row*257 + dOff;
    #pragma unroll
    for (int k=0;k<16;k++){
      float4 v = src[k];
      dstp[4*k+0]=v.x; dstp[4*k+1]=v.y; dstp[4*k+2]=v.z; dstp[4*k+3]=v.w;
    }
  }
  float pnm[2][8], pnu[2];
  #pragma unroll
  for (int si=0;si<2;si++){
    const float* np_ = &g_np[dir][sBase+sl0+si][b][0];
    #pragma unroll
    for (int l=0;l<8;l++) pnm[si][l] = np_[8+l];
    pnu[si] = np_[32];
  }
  float ml[2][8];
  #pragma unroll
  for (int si=0;si<2;si++){
    #pragma unroll
    for (int l=0;l<8;l++) ml[si][l] = -3.4e38f;
  }
  float rs[2] = {0.f,0.f};
  float bv[2] = {-3.4e38f,-3.4e38f};
  int   bi[2] = {0,0};

  for (int tt=0; tt<8; tt++){
    __syncthreads();
    int tBase = tt*32;
    { // Q tile [32 t][256 d]
      int row = tid>>3, dOff=(tid&7)*32;
      const float4* src = (const float4*)(Q + (size_t)((tBase+row)*NB + b)*512 + dir*256 + dOff);
      float* dstq = sQ + row*257 + dOff;
      #pragma unroll
      for (int k=0;k<8;k++){
        float4 v = src[k];
        dstq[4*k+0]=v.x; dstq[4*k+1]=v.y; dstq[4*k+2]=v.z; dstq[4*k+3]=v.w;
      }
    }
    for (int i=tid;i<32*9;i+=256){
      int t=i/9, k=i%9;
      sQn[t*9+k] = g_nq[dir][tBase+t][b][(k<8)?(8+k):32];
    }
    __syncthreads();

    float acc[9][2][4];
    #pragma unroll
    for (int c=0;c<9;c++){
      #pragma unroll
      for(int si=0;si<2;si++){
        #pragma unroll
        for(int j=0;j<4;j++) acc[c][si][j]=0.f;
      }
    }
    const float* pr0p = sP + sl0*257;
    const float* pr1p = sP + (sl0+1)*257;
    for (int d=0; d<D; d++){
      float p0 = pr0p[d];
      float p1 = pr1p[d];
      float q[4];
      #pragma unroll
      for (int j=0;j<4;j++) q[j] = sQ[(tx*4+j)*257 + d];
      float pr0[4], pr1[4];
      #pragma unroll
      for (int j=0;j<4;j++){ pr0[j]=p0*q[j]; pr1[j]=p1*q[j]; }
      #pragma unroll
      for (int c=0;c<9;c++){
        float w = sW[c*D+d];
        #pragma unroll
        for (int j=0;j<4;j++){
          acc[c][0][j] += pr0[j]*w;
          acc[c][1][j] += pr1[j]*w;
        }
      }
    }
    // per-tile epilogue: maxpool running max + alpha write + row stats
    #pragma unroll
    for (int si=0;si<2;si++){
      float a4[4];
      #pragma unroll
      for (int j=0;j<4;j++){
        int tl = tx*4+j;
        #pragma unroll
        for (int l=0;l<8;l++){
          float v = acc[l][si][j] / fmaxf(pnm[si][l]*sQn[tl*9+l], EPS);
          ml[si][l] = fmaxf(ml[si][l], v);
        }
        float al = acc[8][si][j] / fmaxf(pnu[si]*sQn[tl*9+8], EPS);
        a4[j] = al;
        rs[si] += al;
        if (al > bv[si]){ bv[si]=al; bi[si]=tBase+tl; }
      }
      float4* ap = (float4*)&g_alpha[dir][b][sBase+sl0+si][tBase + tx*4];
      *ap = make_float4(a4[0],a4[1],a4[2],a4[3]);
    }
  }
  // reduce across tx (lanes 0..7 share s rows)
  #pragma unroll
  for (int off=1; off<8; off<<=1){
    #pragma unroll
    for (int si=0;si<2;si++){
      rs[si] += __shfl_xor_sync(0xffffffffu, rs[si], off);
      float ov = __shfl_xor_sync(0xffffffffu, bv[si], off);
      int   oi = __shfl_xor_sync(0xffffffffu, bi[si], off);
      if (ov > bv[si] || (ov == bv[si] && oi < bi[si])){ bv[si]=ov; bi[si]=oi; }
      #pragma unroll
      for (int l=0;l<8;l++) ml[si][l] = fmaxf(ml[si][l], __shfl_xor_sync(0xffffffffu, ml[si][l], off));
    }
  }
  if (tx==0){
    #pragma unroll
    for (int si=0;si<2;si++){
      int sg = sBase + sl0 + si;
      g_rowsum[dir][b][sg] = rs[si];
      g_amax[dir][b][sg]   = bi[si];
      float* o = out + ((size_t)sg*NB + b)*64 + 16 + dir*8;
      #pragma unroll
      for (int l=0;l<8;l++) o[l] = ml[si][l];
    }
  }
}

// ---------------- K_hmean: h = (alpha @ Q) / rowsum ----------------
#define SM_H ((64*257 + 32*257)*4)

__global__ void __launch_bounds__(256) k_hmean(const float* __restrict__ Q){
  extern __shared__ float sm[];
  float* sA = sm;             // [64 s][257] (256 t)
  float* sQ = sm + 64*257;    // [32 t][257] (256 d)
  int sTile=blockIdx.x, b=blockIdx.y, dir=blockIdx.z;
  int sBase = sTile*64;
  int tid=threadIdx.x;
  int tx = tid & 15, ty = tid >> 4;
  {
    int row=tid>>2, tOff=(tid&3)*64;
    const float4* src=(const float4*)&g_alpha[dir][b][sBase+row][tOff];
    float* dsta = sA + row*257 + tOff;
    #pragma unroll
    for (int k=0;k<16;k++){
      float4 v=src[k];
      dsta[4*k+0]=v.x; dsta[4*k+1]=v.y; dsta[4*k+2]=v.z; dsta[4*k+3]=v.w;
    }
  }
  float acc[4][16];
  #pragma unroll
  for (int i=0;i<4;i++){
    #pragma unroll
    for(int k2=0;k2<16;k2++) acc[i][k2]=0.f;
  }
  int dBase = tx*16;
  for (int tt=0;tt<8;tt++){
    __syncthreads();
    int tBase=tt*32;
    {
      int row=tid>>3, dOff=(tid&7)*32;
      const float4* src=(const float4*)(Q + (size_t)((tBase+row)*NB+b)*512 + dir*256 + dOff);
      float* dstq = sQ + row*257 + dOff;
      #pragma unroll
      for (int k=0;k<8;k++){
        float4 v=src[k];
        dstq[4*k+0]=v.x; dstq[4*k+1]=v.y; dstq[4*k+2]=v.z; dstq[4*k+3]=v.w;
      }
    }
    __syncthreads();
    for (int t=0;t<32;t++){
      float a[4];
      #pragma unroll
      for (int i=0;i<4;i++) a[i] = sA[(ty*4+i)*257 + tBase + t];
      const float* qr = sQ + t*257 + dBase;
      #pragma unroll
      for (int i=0;i<4;i++){
        #pragma unroll
        for (int k2=0;k2<16;k2++) acc[i][k2] += a[i]*qr[k2];
      }
    }
  }
  #pragma unroll
  for (int i=0;i<4;i++){
    int sg = sBase + ty*4 + i;
    float inv = 1.0f / g_rowsum[dir][b][sg];
    float* o = &g_h[dir][b][sg][dBase];
    #pragma unroll
    for (int k2=0;k2<16;k2++) o[k2] = acc[i][k2]*inv;
  }
}

// ---------------- K_epi: full-match, attentive, max-attentive ----------------
// grid (256 s, 128 b), block 64: warp0=fw, warp1=bw.
__global__ void __launch_bounds__(64) k_epi(const float* __restrict__ P,
                                            const float* __restrict__ Q,
                                            float* __restrict__ out){
  int s = blockIdx.x, b = blockIdx.y;
  int tid=threadIdx.x;
  int dir = tid>>5, lane = tid&31;
  const float* p  = P + (size_t)(s*NB+b)*512 + dir*256;
  int qpos = dir ? 0 : (S-1);
  const float* qf = Q + (size_t)(qpos*NB+b)*512 + dir*256;
  int ts = g_amax[dir][b][s];
  const float* qm = Q + (size_t)(ts*NB+b)*512 + dir*256;
  const float* h  = &g_h[dir][b][s][0];
  float aF[8], aA[8], aH[8], aM[8];
  #pragma unroll
  for (int l=0;l<8;l++){ aF[l]=0.f;aA[l]=0.f;aH[l]=0.f;aM[l]=0.f; }
  #pragma unroll
  for (int k=0;k<8;k++){
    int d = lane + 32*k;
    float pv=p[d], qv=qf[d], hv=h[d], mv=qm[d];
    float pq=pv*qv, ph=pv*hv, hh=hv*hv, pm=pv*mv;
    #pragma unroll
    for (int l=0;l<8;l++){
      aF[l] += pq*g_w2[dir][l][d];
      float w4 = g_w2[4][l][d];
      aA[l] += ph*w4;
      aH[l] += hh*w4;
      aM[l] += pm*g_w2[5][l][d];
    }
  }
  #pragma unroll
  for (int off=16; off; off>>=1){
    #pragma unroll
    for (int l=0;l<8;l++){
      aF[l]+=__shfl_down_sync(0xffffffffu,aF[l],off);
      aA[l]+=__shfl_down_sync(0xffffffffu,aA[l],off);
      aH[l]+=__shfl_down_sync(0xffffffffu,aH[l],off);
      aM[l]+=__shfl_down_sync(0xffffffffu,aM[l],off);
    }
  }
  if (lane==0){
    const float* np_ = &g_np[dir][s][b][0];
    const float* nqf = &g_nq[dir][qpos][b][0];
    const float* nqm = &g_nq[dir][ts][b][0];
    float* o = out + ((size_t)s*NB+b)*64;
    #pragma unroll
    for (int l=0;l<8;l++){
      o[0  + dir*8 + l] = aF[l] / fmaxf(np_[l]    * nqf[l],       EPS);
      o[32 + dir*8 + l] = aA[l] / fmaxf(np_[16+l] * sqrtf(aH[l]), EPS);
      o[48 + dir*8 + l] = aM[l] / fmaxf(np_[24+l] * nqm[24+l],    EPS);
    }
  }
}

extern "C" void kernel_launch(void* const* d_in, const int* in_sizes, int n_in,
                              void* d_out, int out_size){
  const float* P = (const float*)d_in[0];
  const float* Q = (const float*)d_in[1];
  const float* W = (const float*)d_in[2];
  float* out = (float*)d_out;

  cudaFuncSetAttribute(k_main,  cudaFuncAttributeMaxDynamicSharedMemorySize, SM_MAIN);
  cudaFuncSetAttribute(k_hmean, cudaFuncAttributeMaxDynamicSharedMemorySize, SM_H);

  k_w2<<<12, 1024>>>(W);
  k_norms<<<2048, 128>>>(P, Q);
  k_main<<<dim3(4, NB, 2), 256, SM_MAIN>>>(P, Q, out);
  k_hmean<<<dim3(4, NB, 2), 256, SM_H>>>(Q);
  k_epi<<<dim3(S, NB), 64>>>(P, Q, out);
}

// round 3
// speedup vs baseline: 1.3833x; 1.3833x over previous
#include <cuda_runtime.h>
#include <math.h>

#define S 256
#define NB 128
#define D 256
#define L 8
#define EPS 1e-8f

typedef unsigned long long ull;

#define MUL2(d_, a_, b_) asm("mul.rn.f32x2 %0, %1, %2;" : "=l"(d_) : "l"(a_), "l"(b_))
#define ADD2(d_, a_, b_) asm("add.rn.f32x2 %0, %1, %2;" : "=l"(d_) : "l"(a_), "l"(b_))
#define FMA2(d_, a_, b_, c_) asm("fma.rn.f32x2 %0, %1, %2, %3;" : "=l"(d_) : "l"(a_), "l"(b_), "l"(c_))
#define PACK2(d_, x_) asm("mov.b64 %0, {%1, %1};" : "=l"(d_) : "f"(x_))
#define UNPACK2(lo_, hi_, p_) asm("mov.b64 {%0, %1}, %2;" : "=f"(lo_), "=f"(hi_) : "l"(p_))

// ---- scratch (static device memory; no allocations anywhere) ----
__device__ __align__(16) float g_w2[6][L][D];        // W[0..5]^2
// norm slots: 0-7 full(W0/W1), 8-15 maxpool(W2/W3), 16-23 W4, 24-31 W5, 32 unweighted
__device__ __align__(16) float g_np[2][S][NB][33];   // [dir][pos][b][slot]
__device__ __align__(16) float g_nq[2][S][NB][33];
__device__ __align__(16) float g_alpha[2][NB][S][S]; // [dir][b][s][t]
__device__ __align__(16) float g_rowsum[2][NB][S];
__device__ __align__(16) int   g_amax[2][NB][S];
__device__ __align__(16) float g_h[2][NB][S][D];     // h_mean (already divided by rowsum)

// ---------------- K0: W^2 ----------------
__global__ void k_w2(const float* __restrict__ W){
  int i = blockIdx.x*blockDim.x + threadIdx.x;
  if (i < 6*L*D){ float w = W[i]; (&g_w2[0][0][0])[i] = w*w; }
}

// ---------------- K1: all weighted norms ----------------
__global__ void __launch_bounds__(128) k_norms(const float* __restrict__ P,
                                               const float* __restrict__ Q){
  __shared__ float sw[6*L*D];
  int tid = threadIdx.x;
  for (int i=tid; i<6*L*D; i+=128) sw[i] = (&g_w2[0][0][0])[i];
  __syncthreads();
  int warp = tid>>5, lane = tid&31;
  int tensor = warp>>1, dir = warp&1;
  const float* X = tensor ? Q : P;
  float* dst = tensor ? &g_nq[0][0][0][0] : &g_np[0][0][0][0];
  int wrow0 = dir, wrow1 = 2+dir;
  for (int it=0; it<16; it++){
    int r = blockIdx.x*16 + it;
    int pos = r>>7, b = r&127;
    const float* x = X + (size_t)(pos*NB+b)*512 + dir*256;
    float acc[4][L];
    #pragma unroll
    for (int a=0;a<4;a++){
      #pragma unroll
      for (int l=0;l<L;l++) acc[a][l]=0.f;
    }
    float u=0.f;
    #pragma unroll
    for (int k=0;k<8;k++){
      int d = lane + k*32;
      float v = x[d];
      float v2 = v*v;
      u += v2;
      int rows[4] = {wrow0, wrow1, 4, 5};
      #pragma unroll
      for (int a=0;a<4;a++){
        const float* wr = &sw[rows[a]*L*D + d];
        #pragma unroll
        for (int l=0;l<L;l++) acc[a][l] += v2 * wr[l*D];
      }
    }
    #pragma unroll
    for (int off=16; off; off>>=1){
      u += __shfl_down_sync(0xffffffffu, u, off);
      #pragma unroll
      for (int a=0;a<4;a++){
        #pragma unroll
        for (int l=0;l<L;l++) acc[a][l] += __shfl_down_sync(0xffffffffu, acc[a][l], off);
      }
    }
    if (lane==0){
      float* o = dst + ((size_t)(dir*S + pos)*NB + b)*33;
      #pragma unroll
      for (int a=0;a<4;a++){
        #pragma unroll
        for (int l=0;l<L;l++) o[a*8+l] = sqrtf(acc[a][l]);
      }
      o[32] = sqrtf(u);
    }
  }
}

// ---------------- K_main: 9-channel diag-weighted GEMM via f32x2 ----------------
// grid (4 s-tiles, 128 b, 2 dir), block 256. Per CTA: 64 s x 256 t x 256 d x 9 ch.
// smem strides of 258 words keep 8B alignment + conflict-free LDS.64.
#define STRD 258
#define SM_MAIN ((80*STRD + 8*256 + 16*9 + 64*9)*4)

__global__ void __launch_bounds__(256) k_main(const float* __restrict__ P,
                                              const float* __restrict__ Q,
                                              float* __restrict__ out){
  extern __shared__ float sm[];
  float* sP  = sm;                 // [64][258]
  float* sQ  = sm + 64*STRD;       // [16][258]
  float* sW  = sm + 80*STRD;       // [8][256]  maxpool W^2 channels
  float* sQn = sW + 8*256;         // [16][9]
  float* sPn = sQn + 16*9;         // [64][9]  p norms: 0-7 maxpool, 8 unweighted

  int sTile = blockIdx.x, b = blockIdx.y, dir = blockIdx.z;
  int sBase = sTile*64;
  int tid = threadIdx.x;
  int tx = tid & 7, ty = tid >> 3;   // ty: 0..31
  int sl0 = ty*2;

  for (int i=tid;i<8*D;i+=256) sW[i] = g_w2[2+dir][0][i];
  { // P tile [64 s][256 d]
    int row = tid>>2, dOff=(tid&3)*64;
    const float4* src = (const float4*)(P + (size_t)((sBase+row)*NB + b)*512 + dir*256 + dOff);
    float2* dstp = (float2*)(sP + row*STRD + dOff);
    #pragma unroll
    for (int k=0;k<16;k++){
      float4 v = src[k];
      dstp[2*k+0]=make_float2(v.x,v.y); dstp[2*k+1]=make_float2(v.z,v.w);
    }
  }
  for (int i=tid;i<64*9;i+=256){
    int row=i/9, slot=i%9;
    sPn[i] = g_np[dir][sBase+row][b][(slot<8)?(8+slot):32];
  }

  float ml[2][8];
  #pragma unroll
  for (int si=0;si<2;si++){
    #pragma unroll
    for (int l=0;l<8;l++) ml[si][l] = -3.4e38f;
  }
  float rs[2] = {0.f,0.f};
  float bv[2] = {-3.4e38f,-3.4e38f};
  int   bi[2] = {0,0};

  const ull* pA = (const ull*)(sP + sl0*STRD);
  const ull* pB = (const ull*)(sP + (sl0+1)*STRD);
  const ull* wp = (const ull*)sW;

  for (int tt=0; tt<16; tt++){
    __syncthreads();
    int tBase = tt*16;
    { // Q tile [16 t][256 d]
      int row = tid>>4, dOff=(tid&15)*16;
      const float4* src = (const float4*)(Q + (size_t)((tBase+row)*NB + b)*512 + dir*256 + dOff);
      float2* dstq = (float2*)(sQ + row*STRD + dOff);
      #pragma unroll
      for (int k=0;k<4;k++){
        float4 v = src[k];
        dstq[2*k+0]=make_float2(v.x,v.y); dstq[2*k+1]=make_float2(v.z,v.w);
      }
    }
    if (tid < 16*9){
      int t=tid/9, k=tid%9;
      sQn[tid] = g_nq[dir][tBase+t][b][(k<8)?(8+k):32];
    }
    __syncthreads();

    ull acc[9][2][2];
    #pragma unroll
    for (int c=0;c<9;c++){
      #pragma unroll
      for(int si=0;si<2;si++){ acc[c][si][0]=0ULL; acc[c][si][1]=0ULL; }
    }
    const ull* q0p = (const ull*)(sQ + (tx*2+0)*STRD);
    const ull* q1p = (const ull*)(sQ + (tx*2+1)*STRD);
    #pragma unroll 4
    for (int d2=0; d2<128; d2++){
      ull p0 = pA[d2], p1 = pB[d2];
      ull q0 = q0p[d2], q1 = q1p[d2];
      ull r00,r01,r10,r11;
      MUL2(r00,p0,q0); MUL2(r01,p0,q1); MUL2(r10,p1,q0); MUL2(r11,p1,q1);
      ADD2(acc[8][0][0], acc[8][0][0], r00);
      ADD2(acc[8][0][1], acc[8][0][1], r01);
      ADD2(acc[8][1][0], acc[8][1][0], r10);
      ADD2(acc[8][1][1], acc[8][1][1], r11);
      #pragma unroll
      for (int c=0;c<8;c++){
        ull w = wp[c*128 + d2];
        FMA2(acc[c][0][0], r00, w, acc[c][0][0]);
        FMA2(acc[c][0][1], r01, w, acc[c][0][1]);
        FMA2(acc[c][1][0], r10, w, acc[c][1][0]);
        FMA2(acc[c][1][1], r11, w, acc[c][1][1]);
      }
    }
    // per-tile epilogue
    #pragma unroll
    for (int si=0;si<2;si++){
      const float* pn = sPn + (sl0+si)*9;
      float a2[2];
      #pragma unroll
      for (int j=0;j<2;j++){
        int tl = tx*2+j;
        #pragma unroll
        for (int l=0;l<8;l++){
          float lo,hi; UNPACK2(lo,hi,acc[l][si][j]);
          float v = (lo+hi) / fmaxf(pn[l]*sQn[tl*9+l], EPS);
          ml[si][l] = fmaxf(ml[si][l], v);
        }
        float lo,hi; UNPACK2(lo,hi,acc[8][si][j]);
        float al = (lo+hi) / fmaxf(pn[8]*sQn[tl*9+8], EPS);
        a2[j] = al;
        rs[si] += al;
        if (al > bv[si]){ bv[si]=al; bi[si]=tBase+tl; }
      }
      float2* ap = (float2*)&g_alpha[dir][b][sBase+sl0+si][tBase + tx*2];
      *ap = make_float2(a2[0],a2[1]);
    }
  }
  // reduce across tx (8 lanes share s rows)
  #pragma unroll
  for (int off=1; off<8; off<<=1){
    #pragma unroll
    for (int si=0;si<2;si++){
      rs[si] += __shfl_xor_sync(0xffffffffu, rs[si], off);
      float ov = __shfl_xor_sync(0xffffffffu, bv[si], off);
      int   oi = __shfl_xor_sync(0xffffffffu, bi[si], off);
      if (ov > bv[si] || (ov == bv[si] && oi < bi[si])){ bv[si]=ov; bi[si]=oi; }
      #pragma unroll
      for (int l=0;l<8;l++) ml[si][l] = fmaxf(ml[si][l], __shfl_xor_sync(0xffffffffu, ml[si][l], off));
    }
  }
  if (tx==0){
    #pragma unroll
    for (int si=0;si<2;si++){
      int sg = sBase + sl0 + si;
      g_rowsum[dir][b][sg] = rs[si];
      g_amax[dir][b][sg]   = bi[si];
      float* o = out + ((size_t)sg*NB + b)*64 + 16 + dir*8;
      #pragma unroll
      for (int l=0;l<8;l++) o[l] = ml[si][l];
    }
  }
}

// ---------------- K_hmean: h = (alpha @ Q) / rowsum, f32x2 over d ----------------
#define SM_H ((96*STRD)*4)

__global__ void __launch_bounds__(256) k_hmean(const float* __restrict__ Q){
  extern __shared__ float sm[];
  float* sA = sm;              // [64 s][258] (256 t)
  float* sQ = sm + 64*STRD;    // [32 t][258] (256 d)
  int sTile=blockIdx.x, b=blockIdx.y, dir=blockIdx.z;
  int sBase = sTile*64;
  int tid=threadIdx.x;
  int tx = tid & 15, ty = tid >> 4;
  {
    int row=tid>>2, tOff=(tid&3)*64;
    const float4* src=(const float4*)&g_alpha[dir][b][sBase+row][tOff];
    float2* dsta = (float2*)(sA + row*STRD + tOff);
    #pragma unroll
    for (int k=0;k<16;k++){
      float4 v=src[k];
      dsta[2*k+0]=make_float2(v.x,v.y); dsta[2*k+1]=make_float2(v.z,v.w);
    }
  }
  ull acc[4][8];
  #pragma unroll
  for (int i=0;i<4;i++){
    #pragma unroll
    for(int k2=0;k2<8;k2++) acc[i][k2]=0ULL;
  }
  for (int tt=0;tt<8;tt++){
    __syncthreads();
    int tBase=tt*32;
    {
      int row=tid>>3, dOff=(tid&7)*32;
      const float4* src=(const float4*)(Q + (size_t)((tBase+row)*NB+b)*512 + dir*256 + dOff);
      float2* dstq = (float2*)(sQ + row*STRD + dOff);
      #pragma unroll
      for (int k=0;k<8;k++){
        float4 v=src[k];
        dstq[2*k+0]=make_float2(v.x,v.y); dstq[2*k+1]=make_float2(v.z,v.w);
      }
    }
    __syncthreads();
    for (int t=0;t<32;t++){
      ull ap[4];
      #pragma unroll
      for (int i=0;i<4;i++){
        float a = sA[(ty*4+i)*STRD + tBase + t];
        PACK2(ap[i], a);
      }
      const float* qr = sQ + t*STRD + tx*2;
      #pragma unroll
      for (int k2=0;k2<8;k2++){
        ull qp = *(const ull*)(qr + 32*k2);
        #pragma unroll
        for (int i=0;i<4;i++) FMA2(acc[i][k2], ap[i], qp, acc[i][k2]);
      }
    }
  }
  #pragma unroll
  for (int i=0;i<4;i++){
    int sg = sBase + ty*4 + i;
    float inv = 1.0f / g_rowsum[dir][b][sg];
    float* o = &g_h[dir][b][sg][0];
    #pragma unroll
    for (int k2=0;k2<8;k2++){
      float lo,hi; UNPACK2(lo,hi,acc[i][k2]);
      *(float2*)(o + tx*2 + 32*k2) = make_float2(lo*inv, hi*inv);
    }
  }
}

// ---------------- K_epi: full-match, attentive, max-attentive ----------------
__global__ void __launch_bounds__(64) k_epi(const float* __restrict__ P,
                                            const float* __restrict__ Q,
                                            float* __restrict__ out){
  int s = blockIdx.x, b = blockIdx.y;
  int tid=threadIdx.x;
  int dir = tid>>5, lane = tid&31;
  const float* p  = P + (size_t)(s*NB+b)*512 + dir*256;
  int qpos = dir ? 0 : (S-1);
  const float* qf = Q + (size_t)(qpos*NB+b)*512 + dir*256;
  int ts = g_amax[dir][b][s];
  const float* qm = Q + (size_t)(ts*NB+b)*512 + dir*256;
  const float* h  = &g_h[dir][b][s][0];
  float aF[8], aA[8], aH[8], aM[8];
  #pragma unroll
  for (int l=0;l<8;l++){ aF[l]=0.f;aA[l]=0.f;aH[l]=0.f;aM[l]=0.f; }
  #pragma unroll
  for (int k=0;k<8;k++){
    int d = lane + 32*k;
    float pv=p[d], qv=qf[d], hv=h[d], mv=qm[d];
    float pq=pv*qv, ph=pv*hv, hh=hv*hv, pm=pv*mv;
    #pragma unroll
    for (int l=0;l<8;l++){
      aF[l] += pq*g_w2[dir][l][d];
      float w4 = g_w2[4][l][d];
      aA[l] += ph*w4;
      aH[l] += hh*w4;
      aM[l] += pm*g_w2[5][l][d];
    }
  }
  #pragma unroll
  for (int off=16; off; off>>=1){
    #pragma unroll
    for (int l=0;l<8;l++){
      aF[l]+=__shfl_down_sync(0xffffffffu,aF[l],off);
      aA[l]+=__shfl_down_sync(0xffffffffu,aA[l],off);
      aH[l]+=__shfl_down_sync(0xffffffffu,aH[l],off);
      aM[l]+=__shfl_down_sync(0xffffffffu,aM[l],off);
    }
  }
  if (lane==0){
    const float* np_ = &g_np[dir][s][b][0];
    const float* nqf = &g_nq[dir][qpos][b][0];
    const float* nqm = &g_nq[dir][ts][b][0];
    float* o = out + ((size_t)s*NB+b)*64;
    #pragma unroll
    for (int l=0;l<8;l++){
      o[0  + dir*8 + l] = aF[l] / fmaxf(np_[l]    * nqf[l],       EPS);
      o[32 + dir*8 + l] = aA[l] / fmaxf(np_[16+l] * sqrtf(aH[l]), EPS);
      o[48 + dir*8 + l] = aM[l] / fmaxf(np_[24+l] * nqm[24+l],    EPS);
    }
  }
}

extern "C" void kernel_launch(void* const* d_in, const int* in_sizes, int n_in,
                              void* d_out, int out_size){
  const float* P = (const float*)d_in[0];
  const float* Q = (const float*)d_in[1];
  const float* W = (const float*)d_in[2];
  float* out = (float*)d_out;

  cudaFuncSetAttribute(k_main,  cudaFuncAttributeMaxDynamicSharedMemorySize, SM_MAIN);
  cudaFuncSetAttribute(k_hmean, cudaFuncAttributeMaxDynamicSharedMemorySize, SM_H);

  k_w2<<<12, 1024>>>(W);
  k_norms<<<2048, 128>>>(P, Q);
  k_main<<<dim3(4, NB, 2), 256, SM_MAIN>>>(P, Q, out);
  k_hmean<<<dim3(4, NB, 2), 256, SM_H>>>(Q);
  k_epi<<<dim3(S, NB), 64>>>(P, Q, out);
}